// round 4
// baseline (speedup 1.0000x reference)
#include <cuda_runtime.h>
#include <cstdint>

// Shapes (fixed): B=4, N=1024, C=64
#define B_ 4
#define N_ 1024
#define C_ 64
#define M_ (B_ * N_)
#define TI 8

typedef unsigned long long u64;

__device__ float g_x1[M_ * C_];
__device__ float g_x2[M_ * C_];

__device__ __forceinline__ float tanh_fast(float x) {
    float y; asm("tanh.approx.f32 %0, %1;" : "=f"(y) : "f"(x)); return y;
}
__device__ __forceinline__ u64 pk(float lo, float hi) {
    u64 r; asm("mov.b64 %0, {%1, %2};" : "=l"(r) : "f"(lo), "f"(hi)); return r;
}
__device__ __forceinline__ float2 upk(u64 v) {
    float2 f; asm("mov.b64 {%0, %1}, %2;" : "=f"(f.x), "=f"(f.y) : "l"(v)); return f;
}
__device__ __forceinline__ u64 add2(u64 a, u64 b) {
    u64 r; asm("add.rn.f32x2 %0, %1, %2;" : "=l"(r) : "l"(a), "l"(b)); return r;
}
__device__ __forceinline__ u64 mul2(u64 a, u64 b) {
    u64 r; asm("mul.rn.f32x2 %0, %1, %2;" : "=l"(r) : "l"(a), "l"(b)); return r;
}
__device__ __forceinline__ u64 fma2(u64 a, u64 b, u64 c) {
    u64 r; asm("fma.rn.f32x2 %0, %1, %2, %3;" : "=l"(r) : "l"(a), "l"(b), "l"(c)); return r;
}

// Eigen ptanh rational coefficients (fp32-accurate on [-7.905, 7.905])
#define TCL 7.90531110763549805f
#define EA1  4.89352455891786e-03f
#define EA3  6.37261928875436e-04f
#define EA5  1.48572235717979e-05f
#define EA7  5.12229709037114e-08f
#define EA9  -8.60467152213735e-11f
#define EA11 2.00018790482477e-13f
#define EA13 -2.76076847742355e-16f
#define EB0  4.89352518554385e-03f
#define EB2  2.26843463243900e-03f
#define EB4  1.18534705686654e-04f
#define EB6  1.19825839466702e-06f

// ---------------------------------------------------------------------------
// Kernel 1: x1 = x @ W1^T, x2 = x @ W2^T (fp32)
// ---------------------------------------------------------------------------
__global__ __launch_bounds__(256) void proj_kernel(
    const float* __restrict__ x,
    const float* __restrict__ W1,
    const float* __restrict__ W2)
{
    __shared__ float W1s[C_ * 65];
    __shared__ float W2s[C_ * 65];
    __shared__ float xs[16 * C_];

    const int tid  = threadIdx.x;
    const int row0 = blockIdx.x * 16;

    for (int k = tid; k < C_ * C_; k += 256) {
        int d = k >> 6, c = k & 63;
        W1s[d * 65 + c] = W1[k];
        W2s[d * 65 + c] = W2[k];
    }
    for (int k = tid; k < 16 * C_; k += 256)
        xs[k] = x[row0 * C_ + k];
    __syncthreads();

    #pragma unroll
    for (int rr = 0; rr < 4; ++rr) {
        int idx = rr * 256 + tid;
        int r = idx >> 6, d = idx & 63;
        float a1 = 0.f, a2 = 0.f;
        #pragma unroll
        for (int c = 0; c < C_; ++c) {
            float xv = xs[r * C_ + c];
            a1 = fmaf(xv, W1s[d * 65 + c], a1);
            a2 = fmaf(xv, W2s[d * 65 + c], a2);
        }
        g_x1[(row0 + r) * C_ + d] = a1;
        g_x2[(row0 + r) * C_ + d] = a2;
    }
}

// ---------------------------------------------------------------------------
// Kernel 2: fused att + softmax. Hybrid tanh:
//   48 of 64 c's: MUFU tanh.approx.f32 (i-paired via f32x2 add/acc)
//   16 of 64 c's: Eigen rational on FMA pipe (f32x2, bit-trick+2-Newton recip)
// Both pipes run concurrently -> beats the pure-MUFU ceiling.
// ---------------------------------------------------------------------------
__global__ __launch_bounds__(256, 4) void att_kernel(
    const float* __restrict__ w3,
    float* __restrict__ out)
{
    __shared__ u64  x1p_s[C_ * 4];     // [c*4+ip] = (x1[2ip][c], x1[2ip+1][c])
    __shared__ u64  w2s[C_];           // (w3[c], w3[c])
    __shared__ float att_s[TI * N_];   // 32 KB
    __shared__ float red[8];

    const int tid  = threadIdx.x;
    const int b    = blockIdx.y;
    const int i0   = blockIdx.x * TI;
    const int lane = tid & 31;
    const int warp = tid >> 5;

    if (tid < C_ * 4) {
        int c = tid >> 2, ip = tid & 3;
        const float* base = g_x1 + (size_t)(b * N_ + i0) * C_;
        x1p_s[tid] = pk(base[(2 * ip) * C_ + c], base[(2 * ip + 1) * C_ + c]);
    }
    if (tid < C_) w2s[tid] = pk(w3[tid], w3[tid]);
    __syncthreads();

    // packed rational constants (thread-invariant)
    const u64 A13_ = pk(EA13, EA13), A11_ = pk(EA11, EA11), A9_ = pk(EA9, EA9);
    const u64 A7_  = pk(EA7, EA7),   A5_  = pk(EA5, EA5),   A3_ = pk(EA3, EA3);
    const u64 A1_  = pk(EA1, EA1);
    const u64 B6_  = pk(EB6, EB6),   B4_  = pk(EB4, EB4);
    const u64 B2_  = pk(EB2, EB2),   B0_  = pk(EB0, EB0);
    const u64 TWO_ = pk(2.0f, 2.0f);

    const float* x2b = g_x2 + (size_t)b * N_ * C_;

    for (int chunk = 0; chunk < 4; ++chunk) {
        const int j = chunk * 256 + tid;
        const float4* xr = reinterpret_cast<const float4*>(x2b + (size_t)j * C_);

        u64 acc2[4] = {0ull, 0ull, 0ull, 0ull};   // packed (0,0)

        for (int g = 0; g < 8; ++g) {             // 8 c's per group
            const float4 v0 = xr[g * 2];
            const float4 v1 = xr[g * 2 + 1];
            const float zs[8] = {v0.x, v0.y, v0.z, v0.w, v1.x, v1.y, v1.z, v1.w};

            // --- MUFU path: c_local 0..5 ---
            #pragma unroll
            for (int k = 0; k < 6; ++k) {
                const int c = g * 8 + k;
                const u64 zz = pk(zs[k], zs[k]);
                const u64 w2 = w2s[c];
                #pragma unroll
                for (int ip = 0; ip < 4; ++ip) {
                    u64 s2 = add2(x1p_s[c * 4 + ip], zz);
                    float2 s = upk(s2);
                    u64 t2 = pk(tanh_fast(s.x), tanh_fast(s.y));
                    acc2[ip] = fma2(w2, t2, acc2[ip]);
                }
            }
            // --- FMA-pipe rational path: c_local 6..7 ---
            #pragma unroll
            for (int k = 6; k < 8; ++k) {
                const int c = g * 8 + k;
                const u64 zz = pk(zs[k], zs[k]);
                const u64 w2 = w2s[c];
                #pragma unroll
                for (int ip = 0; ip < 4; ++ip) {
                    u64 s2 = add2(x1p_s[c * 4 + ip], zz);
                    float2 s = upk(s2);
                    s.x = fminf(fmaxf(s.x, -TCL), TCL);
                    s.y = fminf(fmaxf(s.y, -TCL), TCL);
                    const u64 sc = pk(s.x, s.y);
                    const u64 t  = mul2(sc, sc);
                    u64 p = fma2(A13_, t, A11_);
                    p = fma2(p, t, A9_);
                    p = fma2(p, t, A7_);
                    p = fma2(p, t, A5_);
                    p = fma2(p, t, A3_);
                    p = fma2(p, t, A1_);
                    p = mul2(p, sc);
                    u64 q = fma2(B6_, t, B4_);
                    q = fma2(q, t, B2_);
                    q = fma2(q, t, B0_);
                    // reciprocal: bit-trick seed + 2 Newton (FMA pipe only)
                    float2 qf = upk(q);
                    float r0 = __int_as_float(0x7EF311C3 - __float_as_int(qf.x));
                    float r1 = __int_as_float(0x7EF311C3 - __float_as_int(qf.y));
                    u64 r  = pk(r0, r1);
                    u64 nq = q ^ 0x8000000080000000ULL;   // negate both halves
                    u64 e  = fma2(nq, r, TWO_); r = mul2(r, e);
                    e      = fma2(nq, r, TWO_); r = mul2(r, e);
                    const u64 y = mul2(p, r);
                    acc2[ip] = fma2(w2, y, acc2[ip]);
                }
            }
        }
        #pragma unroll
        for (int ip = 0; ip < 4; ++ip) {
            float2 a = upk(acc2[ip]);
            att_s[(2 * ip)     * N_ + j] = a.x;
            att_s[(2 * ip + 1) * N_ + j] = a.y;
        }
    }
    __syncthreads();

    // ---- softmax over each of the TI rows ----
    for (int i = 0; i < TI; ++i) {
        float* row = att_s + i * N_;

        float m = -3.4e38f;
        #pragma unroll
        for (int k = 0; k < 4; ++k) m = fmaxf(m, row[k * 256 + tid]);
        #pragma unroll
        for (int o = 16; o > 0; o >>= 1)
            m = fmaxf(m, __shfl_xor_sync(0xFFFFFFFFu, m, o));
        if (lane == 0) red[warp] = m;
        __syncthreads();
        float bm = red[0];
        #pragma unroll
        for (int w = 1; w < 8; ++w) bm = fmaxf(bm, red[w]);
        __syncthreads();

        float s = 0.f;
        #pragma unroll
        for (int k = 0; k < 4; ++k) {
            float e = __expf(row[k * 256 + tid] - bm);
            row[k * 256 + tid] = e;
            s += e;
        }
        #pragma unroll
        for (int o = 16; o > 0; o >>= 1)
            s += __shfl_xor_sync(0xFFFFFFFFu, s, o);
        if (lane == 0) red[warp] = s;
        __syncthreads();
        float bs = red[0];
        #pragma unroll
        for (int w = 1; w < 8; ++w) bs += red[w];
        const float inv = 1.f / bs;

        float* orow = out + ((size_t)(b * N_ + i0 + i)) * N_;
        #pragma unroll
        for (int k = 0; k < 4; ++k)
            orow[k * 256 + tid] = row[k * 256 + tid] * inv;
        __syncthreads();
    }
}

extern "C" void kernel_launch(void* const* d_in, const int* in_sizes, int n_in,
                              void* d_out, int out_size)
{
    const float* x  = (const float*)d_in[0];
    const float* W1 = (const float*)d_in[1];
    const float* W2 = (const float*)d_in[2];
    const float* w3 = (const float*)d_in[3];
    float* out = (float*)d_out;

    proj_kernel<<<M_ / 16, 256>>>(x, W1, W2);

    dim3 grid(N_ / TI, B_);
    att_kernel<<<grid, 256>>>(w3, out);
}

// round 6
// speedup vs baseline: 1.1546x; 1.1546x over previous
#include <cuda_runtime.h>
#include <cstdint>

// Shapes (fixed): B=4, N=1024, C=64
#define B_ 4
#define N_ 1024
#define C_ 64
#define M_ (B_ * N_)
#define TI 8

typedef unsigned long long u64;

// Prepared projections: channel c with (c&15)>=9 stores tanh(proj), else raw.
__device__ float g_x1[M_ * C_];
__device__ float g_x2[M_ * C_];

__device__ __forceinline__ float tanh_fast(float x) {
    float y; asm("tanh.approx.f32 %0, %1;" : "=f"(y) : "f"(x)); return y;
}
__device__ __forceinline__ u64 pk(float lo, float hi) {
    u64 r; asm("mov.b64 %0, {%1, %2};" : "=l"(r) : "f"(lo), "f"(hi)); return r;
}
__device__ __forceinline__ float2 upk(u64 v) {
    float2 f; asm("mov.b64 {%0, %1}, %2;" : "=f"(f.x), "=f"(f.y) : "l"(v)); return f;
}
__device__ __forceinline__ u64 add2(u64 a, u64 b) {
    u64 r; asm("add.rn.f32x2 %0, %1, %2;" : "=l"(r) : "l"(a), "l"(b)); return r;
}
__device__ __forceinline__ u64 mul2(u64 a, u64 b) {
    u64 r; asm("mul.rn.f32x2 %0, %1, %2;" : "=l"(r) : "l"(a), "l"(b)); return r;
}
__device__ __forceinline__ u64 fma2(u64 a, u64 b, u64 c) {
    u64 r; asm("fma.rn.f32x2 %0, %1, %2, %3;" : "=l"(r) : "l"(a), "l"(b), "l"(c)); return r;
}
// two MUFU tanh on the packed halves; movs coalesce away in SASS
__device__ __forceinline__ u64 tanh2_mufu(u64 x) {
    u64 r;
    asm("{\n\t.reg .f32 a,b;\n\t"
        "mov.b64 {a,b}, %1;\n\t"
        "tanh.approx.f32 a, a;\n\t"
        "tanh.approx.f32 b, b;\n\t"
        "mov.b64 %0, {a,b};\n\t}" : "=l"(r) : "l"(x));
    return r;
}
// packed fast-reciprocal seed (~3.4% err), ALU pipe only
__device__ __forceinline__ u64 rcp2_seed(u64 d) {
    u64 r;
    asm("{\n\t.reg .b32 a,b;\n\t"
        "mov.b64 {a,b}, %1;\n\t"
        "sub.u32 a, 0x7EF311C3, a;\n\t"
        "sub.u32 b, 0x7EF311C3, b;\n\t"
        "mov.b64 %0, {a,b};\n\t}" : "=l"(r) : "l"(d));
    return r;
}
__device__ __forceinline__ u64 neg2(u64 x) { return x ^ 0x8000000080000000ULL; }

// ---------------------------------------------------------------------------
// Kernel 1: projections, with per-channel tanh preparation.
// ---------------------------------------------------------------------------
__global__ __launch_bounds__(256) void proj_kernel(
    const float* __restrict__ x,
    const float* __restrict__ W1,
    const float* __restrict__ W2)
{
    __shared__ float W1s[C_ * 65];
    __shared__ float W2s[C_ * 65];
    __shared__ float xs[16 * C_];

    const int tid  = threadIdx.x;
    const int row0 = blockIdx.x * 16;

    for (int k = tid; k < C_ * C_; k += 256) {
        int d = k >> 6, c = k & 63;
        W1s[d * 65 + c] = W1[k];
        W2s[d * 65 + c] = W2[k];
    }
    for (int k = tid; k < 16 * C_; k += 256)
        xs[k] = x[row0 * C_ + k];
    __syncthreads();

    #pragma unroll
    for (int rr = 0; rr < 4; ++rr) {
        int idx = rr * 256 + tid;
        int r = idx >> 6, d = idx & 63;
        float a1 = 0.f, a2 = 0.f;
        #pragma unroll
        for (int c = 0; c < C_; ++c) {
            float xv = xs[r * C_ + c];
            a1 = fmaf(xv, W1s[d * 65 + c], a1);
            a2 = fmaf(xv, W2s[d * 65 + c], a2);
        }
        const bool idp = (d & 15) >= 9;        // identity-path channel
        g_x1[(row0 + r) * C_ + d] = idp ? tanh_fast(a1) : a1;
        g_x2[(row0 + r) * C_ + d] = idp ? tanh_fast(a2) : a2;
    }
}

// ---------------------------------------------------------------------------
// Kernel 2: fused att + softmax. Per 16-channel group: 9 channels via MUFU
// tanh(a+b); 7 channels via addition theorem (t1+t2)/(1+t1*t2) on FMA+ALU
// pipes (packed f32x2, bit-seed + 2-Newton reciprocal). Pipes overlap.
// ---------------------------------------------------------------------------
__global__ __launch_bounds__(256, 4) void att_kernel(
    const float* __restrict__ w3,
    float* __restrict__ out)
{
    __shared__ u64  x1p_s[C_ * 4];     // [c*4+ip] = (prep1[2ip][c], prep1[2ip+1][c])
    __shared__ u64  w2s[C_];           // (w3[c], w3[c])
    __shared__ float att_s[TI * N_];   // 32 KB
    __shared__ float red[8];

    const int tid  = threadIdx.x;
    const int b    = blockIdx.y;
    const int i0   = blockIdx.x * TI;
    const int lane = tid & 31;
    const int warp = tid >> 5;

    if (tid < C_ * 4) {
        int c = tid >> 2, ip = tid & 3;
        const float* base = g_x1 + (size_t)(b * N_ + i0) * C_;
        x1p_s[tid] = pk(base[(2 * ip) * C_ + c], base[(2 * ip + 1) * C_ + c]);
    }
    if (tid < C_) w2s[tid] = pk(w3[tid], w3[tid]);
    __syncthreads();

    const u64 ONE_ = pk(1.0f, 1.0f);
    const u64 TWO_ = pk(2.0f, 2.0f);

    const float* x2b = g_x2 + (size_t)b * N_ * C_;

    for (int chunk = 0; chunk < 4; ++chunk) {
        const int j = chunk * 256 + tid;
        const float4* xr = reinterpret_cast<const float4*>(x2b + (size_t)j * C_);

        u64 acc2[4] = {0ull, 0ull, 0ull, 0ull};

        for (int g = 0; g < 4; ++g) {            // 16 channels per group
            float zs[16];
            {
                const float4 v0 = xr[g * 4 + 0];
                const float4 v1 = xr[g * 4 + 1];
                const float4 v2 = xr[g * 4 + 2];
                const float4 v3 = xr[g * 4 + 3];
                zs[0]=v0.x; zs[1]=v0.y; zs[2]=v0.z; zs[3]=v0.w;
                zs[4]=v1.x; zs[5]=v1.y; zs[6]=v1.z; zs[7]=v1.w;
                zs[8]=v2.x; zs[9]=v2.y; zs[10]=v2.z; zs[11]=v2.w;
                zs[12]=v3.x; zs[13]=v3.y; zs[14]=v3.z; zs[15]=v3.w;
            }

            // --- MUFU path: channels 0..8 of this group (raw values) ---
            #pragma unroll
            for (int k = 0; k < 9; ++k) {
                const int c = g * 16 + k;
                const u64 zz = pk(zs[k], zs[k]);
                const u64 wc = w2s[c];
                #pragma unroll
                for (int ip = 0; ip < 4; ++ip) {
                    u64 s2 = add2(x1p_s[c * 4 + ip], zz);
                    acc2[ip] = fma2(wc, tanh2_mufu(s2), acc2[ip]);
                }
            }
            // --- identity path: channels 9..15 (pre-tanh'd values) ---
            #pragma unroll
            for (int k = 9; k < 16; ++k) {
                const int c = g * 16 + k;
                const u64 zz = pk(zs[k], zs[k]);   // t2 broadcast pair
                const u64 wc = w2s[c];
                #pragma unroll
                for (int ip = 0; ip < 4; ++ip) {
                    const u64 t1 = x1p_s[c * 4 + ip];
                    u64 num = add2(t1, zz);
                    u64 den = fma2(t1, zz, ONE_);
                    u64 nd  = neg2(den);
                    u64 r   = rcp2_seed(den);
                    u64 e   = fma2(nd, r, TWO_); r = mul2(r, e);
                    e       = fma2(nd, r, TWO_); r = mul2(r, e);
                    u64 t   = mul2(num, r);
                    acc2[ip] = fma2(wc, t, acc2[ip]);
                }
            }
        }
        #pragma unroll
        for (int ip = 0; ip < 4; ++ip) {
            float2 a = upk(acc2[ip]);
            att_s[(2 * ip)     * N_ + j] = a.x;
            att_s[(2 * ip + 1) * N_ + j] = a.y;
        }
    }
    __syncthreads();

    // ---- softmax over each of the TI rows ----
    for (int i = 0; i < TI; ++i) {
        float* row = att_s + i * N_;

        float m = -3.4e38f;
        #pragma unroll
        for (int k = 0; k < 4; ++k) m = fmaxf(m, row[k * 256 + tid]);
        #pragma unroll
        for (int o = 16; o > 0; o >>= 1)
            m = fmaxf(m, __shfl_xor_sync(0xFFFFFFFFu, m, o));
        if (lane == 0) red[warp] = m;
        __syncthreads();
        float bm = red[0];
        #pragma unroll
        for (int w = 1; w < 8; ++w) bm = fmaxf(bm, red[w]);
        __syncthreads();

        float s = 0.f;
        #pragma unroll
        for (int k = 0; k < 4; ++k) {
            float e = __expf(row[k * 256 + tid] - bm);
            row[k * 256 + tid] = e;
            s += e;
        }
        #pragma unroll
        for (int o = 16; o > 0; o >>= 1)
            s += __shfl_xor_sync(0xFFFFFFFFu, s, o);
        if (lane == 0) red[warp] = s;
        __syncthreads();
        float bs = red[0];
        #pragma unroll
        for (int w = 1; w < 8; ++w) bs += red[w];
        const float inv = 1.f / bs;

        float* orow = out + ((size_t)(b * N_ + i0 + i)) * N_;
        #pragma unroll
        for (int k = 0; k < 4; ++k)
            orow[k * 256 + tid] = row[k * 256 + tid] * inv;
        __syncthreads();
    }
}

extern "C" void kernel_launch(void* const* d_in, const int* in_sizes, int n_in,
                              void* d_out, int out_size)
{
    const float* x  = (const float*)d_in[0];
    const float* W1 = (const float*)d_in[1];
    const float* W2 = (const float*)d_in[2];
    const float* w3 = (const float*)d_in[3];
    float* out = (float*)d_out;

    proj_kernel<<<M_ / 16, 256>>>(x, W1, W2);

    dim3 grid(N_ / TI, B_);
    att_kernel<<<grid, 256>>>(w3, out);
}